// round 5
// baseline (speedup 1.0000x reference)
#include <cuda_runtime.h>
#include <cuda_bf16.h>
#include <math.h>
#include <stdint.h>

#define NN 16384
#define MAXE 163840
#define MAXT (MAXE + NN)   // edges + self loops

// ---------------- scratch (device globals; no runtime alloc) ----------------
__device__ float g_h1[NN * 512];      // layer1 GEMM output
__device__ float g_h2in[NN * 512];    // gelu(layer1 attn out)  (input to GEMM2)
__device__ float g_h2[NN * 256];      // layer2 GEMM output
__device__ float g_adst1[NN * 4];
__device__ float g_asrc1[NN * 4];
__device__ float g_adst2[NN];
__device__ float g_asrc2[NN];
__device__ int   g_cnt[NN];
__device__ int   g_rowptr[NN + 1];
__device__ int   g_pos[NN];
__device__ int   g_csrsrc[MAXT];

// ---------------- CSR build ----------------
__global__ void zero_cnt_k() {
    int i = blockIdx.x * blockDim.x + threadIdx.x;
    if (i < NN) g_cnt[i] = 0;
}

__global__ void count_k(const int* __restrict__ dst, int E) {
    int i = blockIdx.x * blockDim.x + threadIdx.x;
    int tot = E + NN;
    if (i < tot) {
        int d = (i < E) ? dst[i] : (i - E);   // self loop for node (i-E)
        atomicAdd(&g_cnt[d], 1);
    }
}

// single block, 1024 threads, 16 elems each -> 16384
__global__ void scan_k() {
    __shared__ int sh[1024];
    int t = threadIdx.x;
    int base = t * 16;
    int local[16];
    int s = 0;
#pragma unroll
    for (int k = 0; k < 16; k++) { local[k] = s; s += g_cnt[base + k]; }
    sh[t] = s;
    __syncthreads();
    for (int off = 1; off < 1024; off <<= 1) {
        int v = (t >= off) ? sh[t - off] : 0;
        __syncthreads();
        sh[t] += v;
        __syncthreads();
    }
    int excl = sh[t] - s;
#pragma unroll
    for (int k = 0; k < 16; k++) {
        g_rowptr[base + k] = excl + local[k];
        g_pos[base + k]    = excl + local[k];
    }
    if (t == 1023) g_rowptr[NN] = sh[1023];
}

__global__ void scatter_k(const int* __restrict__ src, const int* __restrict__ dst, int E) {
    int i = blockIdx.x * blockDim.x + threadIdx.x;
    int tot = E + NN;
    if (i < tot) {
        int s, d;
        if (i < E) { s = src[i]; d = dst[i]; }
        else       { s = i - E;  d = i - E; }
        int p = atomicAdd(&g_pos[d], 1);
        g_csrsrc[p] = s;
    }
}

// ---------------- 3xTF32 tensor-core GEMM ----------------
__device__ __forceinline__ void tf32split(float x, uint32_t& hi, uint32_t& lo) {
    asm("cvt.rna.tf32.f32 %0, %1;" : "=r"(hi) : "f"(x));
    float r = x - __uint_as_float(hi);
    asm("cvt.rna.tf32.f32 %0, %1;" : "=r"(lo) : "f"(r));
}

__device__ __forceinline__ void mma_tf32(float& d0, float& d1, float& d2, float& d3,
                                         uint32_t a0, uint32_t a1, uint32_t a2, uint32_t a3,
                                         uint32_t b0, uint32_t b1) {
    asm volatile(
        "mma.sync.aligned.m16n8k8.row.col.f32.tf32.tf32.f32 "
        "{%0,%1,%2,%3}, {%4,%5,%6,%7}, {%8,%9}, {%0,%1,%2,%3};"
        : "+f"(d0), "+f"(d1), "+f"(d2), "+f"(d3)
        : "r"(a0), "r"(a1), "r"(a2), "r"(a3), "r"(b0), "r"(b1));
}

// C[M,N] = A[M,K] @ B[K,N], row-major. CTA tile 128x64, warp tile 32x32.
// LAYER==1: A = x (param),  C = g_h1,  N=512, K=256
// LAYER==2: A = g_h2in,     C = g_h2,  N=256, K=512
template <int LAYER>
__global__ __launch_bounds__(256, 2) void gemm_tc_k(const float* __restrict__ Ain,
                                                    const float* __restrict__ Bin) {
    const int N = (LAYER == 1) ? 512 : 256;
    const int K = (LAYER == 1) ? 256 : 512;
    const float* A = (LAYER == 1) ? Ain : g_h2in;
    float* C = (LAYER == 1) ? g_h1 : g_h2;

    const int LDA = 36;  // 128 x 32 tile, padded
    const int LDB = 68;  // 32 x 64 tile, padded

    __shared__ float As[128 * LDA];
    __shared__ float Bs[32 * LDB];

    int tid = threadIdx.x;
    int lane = tid & 31, warp = tid >> 5;
    int wm = warp & 3, wn = warp >> 2;       // warp grid 4(M) x 2(N)
    int gid = lane >> 2, tig = lane & 3;

    int m0 = blockIdx.y * 128, n0 = blockIdx.x * 64;

    float acc[2][4][4];
#pragma unroll
    for (int mt = 0; mt < 2; mt++)
#pragma unroll
        for (int nt = 0; nt < 4; nt++)
#pragma unroll
            for (int j = 0; j < 4; j++) acc[mt][nt][j] = 0.f;

    for (int k0 = 0; k0 < K; k0 += 32) {
        // stage A tile 128x32
#pragma unroll
        for (int i = 0; i < 4; i++) {
            int idx = tid + i * 256;
            int r = idx >> 3, c = (idx & 7) * 4;
            float4 v = *(const float4*)(A + (size_t)(m0 + r) * K + k0 + c);
            *(float4*)&As[r * LDA + c] = v;
        }
        // stage B tile 32x64
#pragma unroll
        for (int i = 0; i < 2; i++) {
            int idx = tid + i * 256;
            int r = idx >> 4, c = (idx & 15) * 4;
            float4 v = *(const float4*)(Bin + (size_t)(k0 + r) * N + n0 + c);
            *(float4*)&Bs[r * LDB + c] = v;
        }
        __syncthreads();

#pragma unroll
        for (int kk = 0; kk < 32; kk += 8) {
            uint32_t ahi[2][4], alo[2][4];
            uint32_t bhi[4][2], blo[4][2];
#pragma unroll
            for (int mt = 0; mt < 2; mt++) {
                int r0 = wm * 32 + mt * 16 + gid;
                float f0 = As[r0 * LDA + kk + tig];
                float f1 = As[(r0 + 8) * LDA + kk + tig];
                float f2 = As[r0 * LDA + kk + tig + 4];
                float f3 = As[(r0 + 8) * LDA + kk + tig + 4];
                tf32split(f0, ahi[mt][0], alo[mt][0]);
                tf32split(f1, ahi[mt][1], alo[mt][1]);
                tf32split(f2, ahi[mt][2], alo[mt][2]);
                tf32split(f3, ahi[mt][3], alo[mt][3]);
            }
#pragma unroll
            for (int nt = 0; nt < 4; nt++) {
                int cn = wn * 32 + nt * 8 + gid;
                float g0 = Bs[(kk + tig) * LDB + cn];
                float g1 = Bs[(kk + tig + 4) * LDB + cn];
                tf32split(g0, bhi[nt][0], blo[nt][0]);
                tf32split(g1, bhi[nt][1], blo[nt][1]);
            }
#pragma unroll
            for (int mt = 0; mt < 2; mt++)
#pragma unroll
                for (int nt = 0; nt < 4; nt++) {
                    float* d = acc[mt][nt];
                    // small terms first, then dominant
                    mma_tf32(d[0], d[1], d[2], d[3],
                             alo[mt][0], alo[mt][1], alo[mt][2], alo[mt][3],
                             bhi[nt][0], bhi[nt][1]);
                    mma_tf32(d[0], d[1], d[2], d[3],
                             ahi[mt][0], ahi[mt][1], ahi[mt][2], ahi[mt][3],
                             blo[nt][0], blo[nt][1]);
                    mma_tf32(d[0], d[1], d[2], d[3],
                             ahi[mt][0], ahi[mt][1], ahi[mt][2], ahi[mt][3],
                             bhi[nt][0], bhi[nt][1]);
                }
        }
        __syncthreads();
    }

    // epilogue
#pragma unroll
    for (int mt = 0; mt < 2; mt++)
#pragma unroll
        for (int nt = 0; nt < 4; nt++) {
            int r = m0 + wm * 32 + mt * 16 + gid;
            int cc = n0 + wn * 32 + nt * 8 + tig * 2;
            *(float2*)(C + (size_t)r * N + cc) = make_float2(acc[mt][nt][0], acc[mt][nt][1]);
            *(float2*)(C + (size_t)(r + 8) * N + cc) = make_float2(acc[mt][nt][2], acc[mt][nt][3]);
        }
}

// ---------------- per-node attention scalars ----------------
template <int LAYER>
__global__ void node_att_k(const float* __restrict__ att) {
    const int H = (LAYER == 1) ? 4 : 1;
    const int C = (LAYER == 1) ? 128 : 256;
    const float* hfeat = (LAYER == 1) ? g_h1 : g_h2;
    float* adst = (LAYER == 1) ? g_adst1 : g_adst2;
    float* asrc = (LAYER == 1) ? g_asrc1 : g_asrc2;

    int warp = threadIdx.x >> 5, lane = threadIdx.x & 31;
    int n = blockIdx.x * 4 + warp;
    if (n >= NN) return;
#pragma unroll
    for (int h = 0; h < H; h++) {
        float sd = 0.f, ss = 0.f;
#pragma unroll
        for (int k = 0; k < C / 32; k++) {
            int c = lane + 32 * k;
            float v = hfeat[(size_t)n * H * C + h * C + c];
            sd += v * att[h * 2 * C + c];
            ss += v * att[h * 2 * C + C + c];
        }
#pragma unroll
        for (int off = 16; off > 0; off >>= 1) {
            sd += __shfl_xor_sync(0xffffffffu, sd, off);
            ss += __shfl_xor_sync(0xffffffffu, ss, off);
        }
        if (lane == 0) {
            adst[n * H + h] = sd;
            asrc[n * H + h] = ss;
        }
    }
}

__device__ __forceinline__ float sigmoidf_(float x) { return 1.f / (1.f + __expf(-x)); }

// ---------------- fused single-pass attention + softmax + aggregation ----------------
// Softmax is shift-invariant; alpha is bounded (|alpha| << 88), so we skip the
// max-subtraction and do ONE gather pass per edge: ex = exp(alpha),
// out = sum(ex * h_src) / sum(ex).
// one CTA (128 threads, 4 warps) per destination node
template <int LAYER>
__global__ __launch_bounds__(128) void attn_k(const float* __restrict__ bias,
                                              float* __restrict__ outp) {
    const int H = (LAYER == 1) ? 4 : 1;
    const int C = (LAYER == 1) ? 128 : 256;
    const bool GELU = (LAYER == 1);
    const int D = H * C;
    const int KC = C / 32;
    const float* hfeat = (LAYER == 1) ? g_h1 : g_h2;
    const float* adst  = (LAYER == 1) ? g_adst1 : g_adst2;
    const float* asrc  = (LAYER == 1) ? g_asrc1 : g_asrc2;
    float* out = (LAYER == 1) ? g_h2in : outp;

    int n = blockIdx.x;
    int t = threadIdx.x;
    int warp = t >> 5, lane = t & 31;

    __shared__ float hd[D];
    __shared__ float sh_acc[4][D];
    __shared__ float wred[4][H];
    __shared__ float sh_s[H];

    for (int i = t; i < D; i += 128) hd[i] = hfeat[(size_t)n * D + i];
    __syncthreads();

    int r0 = g_rowptr[n], r1 = g_rowptr[n + 1];

    float ad[H];
#pragma unroll
    for (int h = 0; h < H; h++) ad[h] = adst[n * H + h];

    float acc[H * KC];
#pragma unroll
    for (int i = 0; i < H * KC; i++) acc[i] = 0.f;
    float wsum[H];
#pragma unroll
    for (int h = 0; h < H; h++) wsum[h] = 0.f;

    for (int p = r0 + warp; p < r1; p += 4) {
        int s = g_csrsrc[p];
        const float* hs = hfeat + (size_t)s * D;
        float hv[H * KC];
        float dot[H];
#pragma unroll
        for (int h = 0; h < H; h++) {
            float d = 0.f;
#pragma unroll
            for (int k = 0; k < KC; k++) {
                int idx = h * C + lane + 32 * k;
                float v = hs[idx];
                hv[h * KC + k] = v;
                d = fmaf(v, hd[idx], d);
            }
            dot[h] = d;
        }
#pragma unroll
        for (int h = 0; h < H; h++)
#pragma unroll
            for (int off = 16; off > 0; off >>= 1)
                dot[h] += __shfl_xor_sync(0xffffffffu, dot[h], off);

#pragma unroll
        for (int h = 0; h < H; h++) {
            float al = (ad[h] + asrc[s * H + h]) * sigmoidf_(dot[h]);
            al = (al >= 0.f) ? al : 0.2f * al;     // leaky relu
            float ex = __expf(al);
            wsum[h] += ex;
#pragma unroll
            for (int k = 0; k < KC; k++)
                acc[h * KC + k] = fmaf(ex, hv[h * KC + k], acc[h * KC + k]);
        }
    }

    if (lane == 0)
#pragma unroll
        for (int h = 0; h < H; h++) wred[warp][h] = wsum[h];

    // stage per-warp partials
#pragma unroll
    for (int h = 0; h < H; h++)
#pragma unroll
        for (int k = 0; k < KC; k++)
            sh_acc[warp][h * C + lane + 32 * k] = acc[h * KC + k];
    __syncthreads();

    if (t < H) sh_s[t] = wred[0][t] + wred[1][t] + wred[2][t] + wred[3][t] + 1e-16f;
    __syncthreads();

    for (int i = t; i < D; i += 128) {
        float v = sh_acc[0][i] + sh_acc[1][i] + sh_acc[2][i] + sh_acc[3][i];
        int h = i / C;
        v = v / sh_s[h];
        v += bias[i];
        if (GELU) v = 0.5f * v * (1.f + erff(v * 0.70710678118654752f));
        out[(size_t)n * D + i] = v;
    }
}

// ---------------- launch ----------------
extern "C" void kernel_launch(void* const* d_in, const int* in_sizes, int n_in,
                              void* d_out, int out_size) {
    const float* x    = (const float*)d_in[0];
    const int*   ei   = (const int*)d_in[1];
    const float* W1   = (const float*)d_in[2];
    const float* att1 = (const float*)d_in[3];
    const float* b1   = (const float*)d_in[4];
    const float* W2   = (const float*)d_in[5];
    const float* att2 = (const float*)d_in[6];
    const float* b2   = (const float*)d_in[7];
    float* outp = (float*)d_out;

    int E = in_sizes[1] / 2;
    const int* src = ei;
    const int* dst = ei + E;
    int tot = E + NN;

    // CSR (shared by both layers)
    zero_cnt_k<<<NN / 256, 256>>>();
    count_k<<<(tot + 255) / 256, 256>>>(dst, E);
    scan_k<<<1, 1024>>>();
    scatter_k<<<(tot + 255) / 256, 256>>>(src, dst, E);

    // layer 1
    gemm_tc_k<1><<<dim3(512 / 64, NN / 128), 256>>>(x, W1);
    node_att_k<1><<<NN / 4, 128>>>(att1);
    attn_k<1><<<NN, 128>>>(b1, nullptr);

    // layer 2
    gemm_tc_k<2><<<dim3(256 / 64, NN / 128), 256>>>(nullptr, W2);
    node_att_k<2><<<NN / 4, 128>>>(att2);
    attn_k<2><<<NN, 128>>>(b2, outp);
}

// round 6
// speedup vs baseline: 1.8602x; 1.8602x over previous
#include <cuda_runtime.h>
#include <cuda_bf16.h>
#include <math.h>
#include <stdint.h>

#define NN 16384
#define MAXE 163840
#define MAXT (MAXE + NN)   // edges + self loops

// ---------------- scratch (device globals; no runtime alloc) ----------------
__device__ float g_h1[NN * 512];      // layer1 GEMM output
__device__ float g_h2[NN * 256];      // layer2 GEMM output
__device__ __nv_bfloat16 g_a1hi[NN * 256];
__device__ __nv_bfloat16 g_a1lo[NN * 256];
__device__ __nv_bfloat16 g_a2hi[NN * 512];   // written by attn layer1 epilogue
__device__ __nv_bfloat16 g_a2lo[NN * 512];
__device__ __nv_bfloat16 g_bt1hi[512 * 256]; // W1 transposed [N][K]
__device__ __nv_bfloat16 g_bt1lo[512 * 256];
__device__ __nv_bfloat16 g_bt2hi[256 * 512]; // W2 transposed [N][K]
__device__ __nv_bfloat16 g_bt2lo[256 * 512];
__device__ float g_adst1[NN * 4];
__device__ float g_asrc1[NN * 4];
__device__ float g_adst2[NN];
__device__ float g_asrc2[NN];
__device__ int   g_cnt[NN];
__device__ int   g_rowptr[NN + 1];
__device__ int   g_pos[NN];
__device__ int   g_csrsrc[MAXT];

// ---------------- CSR build ----------------
__global__ void zero_cnt_k() {
    int i = blockIdx.x * blockDim.x + threadIdx.x;
    if (i < NN) g_cnt[i] = 0;
}

__global__ void count_k(const int* __restrict__ dst, int E) {
    int i = blockIdx.x * blockDim.x + threadIdx.x;
    int tot = E + NN;
    if (i < tot) {
        int d = (i < E) ? dst[i] : (i - E);   // self loop for node (i-E)
        atomicAdd(&g_cnt[d], 1);
    }
}

// single block, 1024 threads, 16 elems each -> 16384
__global__ void scan_k() {
    __shared__ int sh[1024];
    int t = threadIdx.x;
    int base = t * 16;
    int local[16];
    int s = 0;
#pragma unroll
    for (int k = 0; k < 16; k++) { local[k] = s; s += g_cnt[base + k]; }
    sh[t] = s;
    __syncthreads();
    for (int off = 1; off < 1024; off <<= 1) {
        int v = (t >= off) ? sh[t - off] : 0;
        __syncthreads();
        sh[t] += v;
        __syncthreads();
    }
    int excl = sh[t] - s;
#pragma unroll
    for (int k = 0; k < 16; k++) {
        g_rowptr[base + k] = excl + local[k];
        g_pos[base + k]    = excl + local[k];
    }
    if (t == 1023) g_rowptr[NN] = sh[1023];
}

__global__ void scatter_k(const int* __restrict__ src, const int* __restrict__ dst, int E) {
    int i = blockIdx.x * blockDim.x + threadIdx.x;
    int tot = E + NN;
    if (i < tot) {
        int s, d;
        if (i < E) { s = src[i]; d = dst[i]; }
        else       { s = i - E;  d = i - E; }
        int p = atomicAdd(&g_pos[d], 1);
        g_csrsrc[p] = s;
    }
}

// ---------------- bf16 hi/lo split helpers ----------------
__device__ __forceinline__ void bf16split(float v, __nv_bfloat16& h, __nv_bfloat16& l) {
    h = __float2bfloat16_rn(v);
    l = __float2bfloat16_rn(v - __bfloat162float(h));
}

__global__ void split_x_k(const float* __restrict__ x) {
    int i = blockIdx.x * blockDim.x + threadIdx.x;
    if (i < NN * 256) {
        __nv_bfloat16 h, l;
        bf16split(x[i], h, l);
        g_a1hi[i] = h;
        g_a1lo[i] = l;
    }
}

// W [KD, ND] row-major -> transposed hi/lo [ND][KD]
template <int KD, int ND, int WHICH>
__global__ void split_wt_k(const float* __restrict__ W) {
    int i = blockIdx.x * blockDim.x + threadIdx.x;
    if (i < KD * ND) {
        int k = i / ND, n = i % ND;   // coalesced read over n
        __nv_bfloat16 h, l;
        bf16split(W[i], h, l);
        if (WHICH == 1) { g_bt1hi[n * KD + k] = h; g_bt1lo[n * KD + k] = l; }
        else            { g_bt2hi[n * KD + k] = h; g_bt2lo[n * KD + k] = l; }
    }
}

// ---------------- bf16 tensor-core GEMM (3-term split) ----------------
__device__ __forceinline__ void ldsm_x4(uint32_t& r0, uint32_t& r1, uint32_t& r2, uint32_t& r3,
                                        uint32_t addr) {
    asm volatile("ldmatrix.sync.aligned.m8n8.x4.shared.b16 {%0,%1,%2,%3}, [%4];"
                 : "=r"(r0), "=r"(r1), "=r"(r2), "=r"(r3) : "r"(addr));
}

__device__ __forceinline__ void mma_bf16(float* d, const uint32_t* a, const uint32_t* b) {
    asm volatile("mma.sync.aligned.m16n8k16.row.col.f32.bf16.bf16.f32 "
                 "{%0,%1,%2,%3}, {%4,%5,%6,%7}, {%8,%9}, {%0,%1,%2,%3};"
                 : "+f"(d[0]), "+f"(d[1]), "+f"(d[2]), "+f"(d[3])
                 : "r"(a[0]), "r"(a[1]), "r"(a[2]), "r"(a[3]), "r"(b[0]), "r"(b[1]));
}

// C[M,N] = A[M,K] @ Bt[N,K]^T.  CTA tile 128x128, 8 warps (2M x 4N), warp tile 64x32.
// LAYER==1: A=g_a1*, B=g_bt1*, C=g_h1, N=512, K=256
// LAYER==2: A=g_a2*, B=g_bt2*, C=g_h2, N=256, K=512
template <int LAYER>
__global__ __launch_bounds__(256, 2) void gemm_bf16_k() {
    const int N = (LAYER == 1) ? 512 : 256;
    const int K = (LAYER == 1) ? 256 : 512;
    const __nv_bfloat16* Ahi = (LAYER == 1) ? g_a1hi : g_a2hi;
    const __nv_bfloat16* Alo = (LAYER == 1) ? g_a1lo : g_a2lo;
    const __nv_bfloat16* Bhi = (LAYER == 1) ? g_bt1hi : g_bt2hi;
    const __nv_bfloat16* Blo = (LAYER == 1) ? g_bt1lo : g_bt2lo;
    float* C = (LAYER == 1) ? g_h1 : g_h2;

    const int LDSW = 40;  // bf16 units per smem row (80B: bank-conflict-free for ldmatrix)
    __shared__ __nv_bfloat16 sA[2][128 * LDSW];
    __shared__ __nv_bfloat16 sB[2][128 * LDSW];

    int tid = threadIdx.x, lane = tid & 31, warp = tid >> 5;
    int wm = warp & 1, wn = warp >> 1;       // 2(M) x 4(N)
    int gid = lane >> 2, tig = lane & 3;
    int m0 = blockIdx.y * 128, n0 = blockIdx.x * 128;

    float acc[4][4][4];
#pragma unroll
    for (int mt = 0; mt < 4; mt++)
#pragma unroll
        for (int nt = 0; nt < 4; nt++)
#pragma unroll
            for (int j = 0; j < 4; j++) acc[mt][nt][j] = 0.f;

    // ldmatrix lane address components
    int lt = lane >> 3, lr = lane & 7;
    int a_row = wm * 64 + (lt & 1) * 8 + lr;      // + mt*16
    int a_colp = (lt >> 1) * 8;                   // + kk
    int b_row = wn * 32 + (lt >> 1) * 8 + lr;     // + pair*16
    int b_colp = (lt & 1) * 8;                    // + kk

    for (int k0 = 0; k0 < K; k0 += 32) {
        // stage tiles: each plane 128 rows x 32 k (float4 = 8 bf16)
#pragma unroll
        for (int i = 0; i < 2; i++) {
            int idx = tid + i * 256;
            int r = idx >> 2, c = (idx & 3) * 8;
            *(float4*)&sA[0][r * LDSW + c] = *(const float4*)(Ahi + (size_t)(m0 + r) * K + k0 + c);
            *(float4*)&sA[1][r * LDSW + c] = *(const float4*)(Alo + (size_t)(m0 + r) * K + k0 + c);
            *(float4*)&sB[0][r * LDSW + c] = *(const float4*)(Bhi + (size_t)(n0 + r) * K + k0 + c);
            *(float4*)&sB[1][r * LDSW + c] = *(const float4*)(Blo + (size_t)(n0 + r) * K + k0 + c);
        }
        __syncthreads();

#pragma unroll
        for (int kk = 0; kk < 32; kk += 16) {
            uint32_t bh[4][2], bl[4][2];
#pragma unroll
            for (int pair = 0; pair < 2; pair++) {
                uint32_t ah_ = (uint32_t)__cvta_generic_to_shared(
                    &sB[0][(b_row + pair * 16) * LDSW + kk + b_colp]);
                ldsm_x4(bh[2 * pair][0], bh[2 * pair][1], bh[2 * pair + 1][0], bh[2 * pair + 1][1], ah_);
                uint32_t al_ = (uint32_t)__cvta_generic_to_shared(
                    &sB[1][(b_row + pair * 16) * LDSW + kk + b_colp]);
                ldsm_x4(bl[2 * pair][0], bl[2 * pair][1], bl[2 * pair + 1][0], bl[2 * pair + 1][1], al_);
            }
#pragma unroll
            for (int mt = 0; mt < 4; mt++) {
                uint32_t ah[4], al[4];
                uint32_t aaddr = (uint32_t)__cvta_generic_to_shared(
                    &sA[0][(a_row + mt * 16) * LDSW + kk + a_colp]);
                ldsm_x4(ah[0], ah[1], ah[2], ah[3], aaddr);
                uint32_t aaddr2 = (uint32_t)__cvta_generic_to_shared(
                    &sA[1][(a_row + mt * 16) * LDSW + kk + a_colp]);
                ldsm_x4(al[0], al[1], al[2], al[3], aaddr2);
#pragma unroll
                for (int nt = 0; nt < 4; nt++) {
                    mma_bf16(acc[mt][nt], al, bh[nt]);   // lo*hi
                    mma_bf16(acc[mt][nt], ah, bl[nt]);   // hi*lo
                    mma_bf16(acc[mt][nt], ah, bh[nt]);   // hi*hi (dominant last)
                }
            }
        }
        __syncthreads();
    }

    // epilogue
#pragma unroll
    for (int mt = 0; mt < 4; mt++)
#pragma unroll
        for (int nt = 0; nt < 4; nt++) {
            int r = m0 + wm * 64 + mt * 16 + gid;
            int cc = n0 + wn * 32 + nt * 8 + 2 * tig;
            *(float2*)(C + (size_t)r * N + cc) = make_float2(acc[mt][nt][0], acc[mt][nt][1]);
            *(float2*)(C + (size_t)(r + 8) * N + cc) = make_float2(acc[mt][nt][2], acc[mt][nt][3]);
        }
}

// ---------------- per-node attention scalars ----------------
template <int LAYER>
__global__ void node_att_k(const float* __restrict__ att) {
    const int H = (LAYER == 1) ? 4 : 1;
    const int C = (LAYER == 1) ? 128 : 256;
    const float* hfeat = (LAYER == 1) ? g_h1 : g_h2;
    float* adst = (LAYER == 1) ? g_adst1 : g_adst2;
    float* asrc = (LAYER == 1) ? g_asrc1 : g_asrc2;

    int warp = threadIdx.x >> 5, lane = threadIdx.x & 31;
    int n = blockIdx.x * 4 + warp;
    if (n >= NN) return;
#pragma unroll
    for (int h = 0; h < H; h++) {
        float sd = 0.f, ss = 0.f;
#pragma unroll
        for (int k = 0; k < C / 32; k++) {
            int c = lane + 32 * k;
            float v = hfeat[(size_t)n * H * C + h * C + c];
            sd += v * att[h * 2 * C + c];
            ss += v * att[h * 2 * C + C + c];
        }
#pragma unroll
        for (int off = 16; off > 0; off >>= 1) {
            sd += __shfl_xor_sync(0xffffffffu, sd, off);
            ss += __shfl_xor_sync(0xffffffffu, ss, off);
        }
        if (lane == 0) {
            adst[n * H + h] = sd;
            asrc[n * H + h] = ss;
        }
    }
}

__device__ __forceinline__ float sigmoidf_(float x) { return 1.f / (1.f + __expf(-x)); }

// ---------------- fused single-pass attention + softmax + aggregation ----------------
// Softmax is shift-invariant; |alpha| << 88, so skip max-subtraction: ONE gather pass.
// one CTA (128 threads, 4 warps) per destination node.
// LAYER==1: in g_h1, out -> bf16 split planes g_a2hi/g_a2lo (input of GEMM2), with GELU
// LAYER==2: in g_h2, out -> outp (f32), no GELU
template <int LAYER>
__global__ __launch_bounds__(128) void attn_k(const float* __restrict__ bias,
                                              float* __restrict__ outp) {
    const int H = (LAYER == 1) ? 4 : 1;
    const int C = (LAYER == 1) ? 128 : 256;
    const int D = H * C;
    const int KC = C / 32;
    const float* hfeat = (LAYER == 1) ? g_h1 : g_h2;
    const float* adst  = (LAYER == 1) ? g_adst1 : g_adst2;
    const float* asrc  = (LAYER == 1) ? g_asrc1 : g_asrc2;

    int n = blockIdx.x;
    int t = threadIdx.x;
    int warp = t >> 5, lane = t & 31;

    __shared__ float hd[D];
    __shared__ float sh_acc[4][D];
    __shared__ float wred[4][H];
    __shared__ float sh_s[H];

    for (int i = t; i < D; i += 128) hd[i] = hfeat[(size_t)n * D + i];
    __syncthreads();

    int r0 = g_rowptr[n], r1 = g_rowptr[n + 1];

    float ad[H];
#pragma unroll
    for (int h = 0; h < H; h++) ad[h] = adst[n * H + h];

    float acc[H * KC];
#pragma unroll
    for (int i = 0; i < H * KC; i++) acc[i] = 0.f;
    float wsum[H];
#pragma unroll
    for (int h = 0; h < H; h++) wsum[h] = 0.f;

    for (int p = r0 + warp; p < r1; p += 4) {
        int s = g_csrsrc[p];
        const float* hs = hfeat + (size_t)s * D;
        float hv[H * KC];
        float dot[H];
#pragma unroll
        for (int h = 0; h < H; h++) {
            float d = 0.f;
#pragma unroll
            for (int k = 0; k < KC; k++) {
                int idx = h * C + lane + 32 * k;
                float v = hs[idx];
                hv[h * KC + k] = v;
                d = fmaf(v, hd[idx], d);
            }
            dot[h] = d;
        }
#pragma unroll
        for (int h = 0; h < H; h++)
#pragma unroll
            for (int off = 16; off > 0; off >>= 1)
                dot[h] += __shfl_xor_sync(0xffffffffu, dot[h], off);

#pragma unroll
        for (int h = 0; h < H; h++) {
            float al = (ad[h] + asrc[s * H + h]) * sigmoidf_(dot[h]);
            al = (al >= 0.f) ? al : 0.2f * al;     // leaky relu
            float ex = __expf(al);
            wsum[h] += ex;
#pragma unroll
            for (int k = 0; k < KC; k++)
                acc[h * KC + k] = fmaf(ex, hv[h * KC + k], acc[h * KC + k]);
        }
    }

    if (lane == 0)
#pragma unroll
        for (int h = 0; h < H; h++) wred[warp][h] = wsum[h];

#pragma unroll
    for (int h = 0; h < H; h++)
#pragma unroll
        for (int k = 0; k < KC; k++)
            sh_acc[warp][h * C + lane + 32 * k] = acc[h * KC + k];
    __syncthreads();

    if (t < H) sh_s[t] = wred[0][t] + wred[1][t] + wred[2][t] + wred[3][t] + 1e-16f;
    __syncthreads();

    for (int i = t; i < D; i += 128) {
        float v = sh_acc[0][i] + sh_acc[1][i] + sh_acc[2][i] + sh_acc[3][i];
        int h = i / C;
        v = v / sh_s[h];
        v += bias[i];
        if (LAYER == 1) {
            v = 0.5f * v * (1.f + erff(v * 0.70710678118654752f));  // exact GELU
            __nv_bfloat16 hh, ll;
            bf16split(v, hh, ll);
            g_a2hi[(size_t)n * D + i] = hh;
            g_a2lo[(size_t)n * D + i] = ll;
        } else {
            outp[(size_t)n * D + i] = v;
        }
    }
}

// ---------------- launch ----------------
extern "C" void kernel_launch(void* const* d_in, const int* in_sizes, int n_in,
                              void* d_out, int out_size) {
    const float* x    = (const float*)d_in[0];
    const int*   ei   = (const int*)d_in[1];
    const float* W1   = (const float*)d_in[2];
    const float* att1 = (const float*)d_in[3];
    const float* b1   = (const float*)d_in[4];
    const float* W2   = (const float*)d_in[5];
    const float* att2 = (const float*)d_in[6];
    const float* b2   = (const float*)d_in[7];
    float* outp = (float*)d_out;

    int E = in_sizes[1] / 2;
    const int* src = ei;
    const int* dst = ei + E;
    int tot = E + NN;

    // CSR (shared by both layers)
    zero_cnt_k<<<NN / 256, 256>>>();
    count_k<<<(tot + 255) / 256, 256>>>(dst, E);
    scan_k<<<1, 1024>>>();
    scatter_k<<<(tot + 255) / 256, 256>>>(src, dst, E);

    // operand splits
    split_x_k<<<NN * 256 / 256, 256>>>(x);
    split_wt_k<256, 512, 1><<<256 * 512 / 256, 256>>>(W1);
    split_wt_k<512, 256, 2><<<512 * 256 / 256, 256>>>(W2);

    // layer 1
    gemm_bf16_k<1><<<dim3(512 / 128, NN / 128), 256>>>();
    node_att_k<1><<<NN / 4, 128>>>(att1);
    attn_k<1><<<NN, 128>>>(b1, nullptr);

    // layer 2
    gemm_bf16_k<2><<<dim3(256 / 128, NN / 128), 256>>>();
    node_att_k<2><<<NN / 4, 128>>>(att2);
    attn_k<2><<<NN, 128>>>(b2, outp);
}